// round 13
// baseline (speedup 1.0000x reference)
#include <cuda_runtime.h>
#include <cuda_bf16.h>

// ---------------------------------------------------------------------------
// GIN layer: out = relu( relu( (x + scatter_sum(x[src] -> dst)) @ W1^T + b1 ) @ W2^T + b2 )
// N = 100000, D = 128, E = 625000.
//
// R12: 64-row MLP tiles (tail balance: max/mean 11/10.56 vs 6/5.28),
//      faster zero kernel. Scatter = R11 proven one-shot bulk-reduce.
// ---------------------------------------------------------------------------

#define D 128
#define MAX_N 100000
#define SA 132
#define SB 136
#define EPB 32           // edges per block in the scatter
#define TROWS 64         // MLP tile rows

__device__ float g_agg[(size_t)MAX_N * D];

// ---------------------------------------------------------------------------
__global__ void zero_agg_kernel(int total4) {
    int i0 = (blockIdx.x * blockDim.x + threadIdx.x) * 4;
    int stride = gridDim.x * blockDim.x * 4;
    for (int i = i0; i < total4; i += stride) {
        float4 z = make_float4(0.f, 0.f, 0.f, 0.f);
        ((float4*)g_agg)[i]     = z;
        if (i + 1 < total4) ((float4*)g_agg)[i + 1] = z;
        if (i + 2 < total4) ((float4*)g_agg)[i + 2] = z;
        if (i + 3 < total4) ((float4*)g_agg)[i + 3] = z;
    }
}

// ---------------------------------------------------------------------------
__device__ __forceinline__ unsigned smem_u32(const void* p) {
    unsigned a;
    asm("{ .reg .u64 t; cvta.to.shared.u64 t, %1; cvt.u32.u64 %0, t; }"
        : "=r"(a) : "l"(p));
    return a;
}

// One-shot bulk-reduce scatter (R11 proven). Block = 128 threads, 32 edges.
__global__ __launch_bounds__(128, 8)
void scatter_bulk_kernel(const float* __restrict__ x,
                         const int* __restrict__ src,
                         const int* __restrict__ dst,
                         int E) {
    __shared__ __align__(16) float buf[EPB][D];   // 16 KB

    const int tid = threadIdx.x;
    const int e0  = blockIdx.x * EPB;

    {
        const int r  = tid >> 2;
        const int c0 = tid & 3;
        int e = e0 + r;
        if (e < E) {
            const float4* xs = (const float4*)(x + (long)src[e] * D);
            float4* bb = (float4*)&buf[r][0];
#pragma unroll
            for (int q = 0; q < 8; ++q) {
                bb[c0 + q * 4] = xs[c0 + q * 4];
            }
        }
    }
    __syncthreads();
    asm volatile("fence.proxy.async.shared::cta;" ::: "memory");

    if (tid < EPB) {
        int e = e0 + tid;
        if (e < E) {
            unsigned saddr = smem_u32(&buf[tid][0]);
            float* g = g_agg + (long)dst[e] * D;
            asm volatile(
                "cp.reduce.async.bulk.global.shared::cta.bulk_group.add.f32 "
                "[%0], [%1], 512;"
                :: "l"(g), "r"(saddr) : "memory");
        }
        asm volatile("cp.async.bulk.commit_group;" ::: "memory");
        asm volatile("cp.async.bulk.wait_group 0;" ::: "memory");
    }
}

// ---------------------------------------------------------------------------
__device__ __forceinline__ unsigned f2tf32(float f) {
    unsigned r;
    asm("cvt.rna.tf32.f32 %0, %1;" : "=r"(r) : "f"(f));
    return r;
}

__device__ __forceinline__ void mma_tf32(float c[4], const unsigned a[4],
                                         const unsigned b[2]) {
    asm volatile(
        "mma.sync.aligned.m16n8k8.row.col.f32.tf32.tf32.f32 "
        "{%0,%1,%2,%3}, {%4,%5,%6,%7}, {%8,%9}, {%0,%1,%2,%3};"
        : "+f"(c[0]), "+f"(c[1]), "+f"(c[2]), "+f"(c[3])
        : "r"(a[0]), "r"(a[1]), "r"(a[2]), "r"(a[3]), "r"(b[0]), "r"(b[1]));
}

// ---------------------------------------------------------------------------
// Persistent fused MLP, 64-row tiles. Grid = 148 CTAs x 256 threads (8 warps).
// Warp grid: 4 row-groups x 2 col-groups -> warp tile 16 rows x 64 cols
// (1 m-tile x 8 n-tiles of m16n8k8). Fragment layout identical to proven R9.
__global__ __launch_bounds__(256, 1)
void mlp_kernel(const float* __restrict__ x,
                const float* __restrict__ W1, const float* __restrict__ b1,
                const float* __restrict__ W2, const float* __restrict__ b2,
                float* __restrict__ out, int n, int numTiles) {
    extern __shared__ float sm[];
    float* Abuf = sm;                     // TROWS*SA
    float* W1t  = sm + TROWS * SA;        // 128*SB
    float* W2t  = W1t + 128 * SB;         // 128*SB

    const int tid  = threadIdx.x;
    const int w    = tid >> 5;
    const int lane = tid & 31;
    const int lr   = lane >> 2;
    const int lc   = lane & 3;
    const int rw   = (w & 3) * 16;    // warp row offset (16-row m-tile)
    const int cw   = (w >> 2) * 64;   // warp col offset
    const int i0   = tid >> 5;        // A staging row group (0..7)
    const int k4   = tid & 31;        // float4 column chunk

    // Stage both weight matrices transposed (tf32) -- once per CTA.
    for (int idx = tid; idx < D * D; idx += 256) {
        int nn = idx >> 7;
        int m  = idx & 127;
        W1t[m * SB + nn] = __uint_as_float(f2tf32(W1[idx]));
        W2t[m * SB + nn] = __uint_as_float(f2tf32(W2[idx]));
    }

    // Prefetch first tile (A = x + agg) into registers: 8 rows per thread.
    float4 r[8];
    int t = blockIdx.x;
    {
        int base = t * TROWS;
#pragma unroll
        for (int q = 0; q < 8; ++q) {
            int row = base + i0 + 8 * q;
            float4 v = make_float4(0.f, 0.f, 0.f, 0.f);
            if (row < n) {
                float4 vx = *(const float4*)(x + (long)row * D + k4 * 4);
                float4 vg = *(const float4*)(g_agg + (long)row * D + k4 * 4);
                v.x = vx.x + vg.x; v.y = vx.y + vg.y;
                v.z = vx.z + vg.z; v.w = vx.w + vg.w;
            }
            r[q] = v;
        }
    }

    for (; t < numTiles; t += gridDim.x) {
        const int row0 = t * TROWS;

        __syncthreads();   // prev iter's GEMM2 reads of Abuf complete; W visible (iter 0)

        // Store prefetched tile (tf32) into Abuf.
#pragma unroll
        for (int q = 0; q < 8; ++q) {
            uint4 u;
            u.x = f2tf32(r[q].x); u.y = f2tf32(r[q].y);
            u.z = f2tf32(r[q].z); u.w = f2tf32(r[q].w);
            *(uint4*)(Abuf + (i0 + 8 * q) * SA + k4 * 4) = u;
        }
        __syncthreads();

        // Prefetch next tile -- overlaps both GEMMs below.
        int tn = t + gridDim.x;
        if (tn < numTiles) {
            int base = tn * TROWS;
#pragma unroll
            for (int q = 0; q < 8; ++q) {
                int row = base + i0 + 8 * q;
                float4 v = make_float4(0.f, 0.f, 0.f, 0.f);
                if (row < n) {
                    float4 vx = *(const float4*)(x + (long)row * D + k4 * 4);
                    float4 vg = *(const float4*)(g_agg + (long)row * D + k4 * 4);
                    v.x = vx.x + vg.x; v.y = vx.y + vg.y;
                    v.z = vx.z + vg.z; v.w = vx.w + vg.w;
                }
                r[q] = v;
            }
        }

        float acc[8][4];
#pragma unroll
        for (int nt = 0; nt < 8; ++nt)
#pragma unroll
            for (int q = 0; q < 4; ++q) acc[nt][q] = 0.f;

        // ---- GEMM 1: acc = A @ W1^T ----
#pragma unroll 4
        for (int ks = 0; ks < 16; ++ks) {
            const int k0 = ks * 8;
            unsigned a[4];
            {
                const float* p = Abuf + (rw + lr) * SA + k0 + lc;
                a[0] = __float_as_uint(p[0]);
                a[1] = __float_as_uint(p[8 * SA]);
                a[2] = __float_as_uint(p[4]);
                a[3] = __float_as_uint(p[8 * SA + 4]);
            }
            unsigned b[8][2];
#pragma unroll
            for (int nt = 0; nt < 8; ++nt) {
                const float* p = W1t + (k0 + lc) * SB + cw + 8 * nt + lr;
                b[nt][0] = __float_as_uint(p[0]);
                b[nt][1] = __float_as_uint(p[4 * SB]);
            }
#pragma unroll
            for (int nt = 0; nt < 8; ++nt) mma_tf32(acc[nt], a, b[nt]);
        }
        __syncthreads();   // all warps done reading Abuf

        // Epilogue 1: bias + relu -> h1 (tf32) back into Abuf.
#pragma unroll
        for (int nt = 0; nt < 8; ++nt) {
            int col = cw + 8 * nt + 2 * lc;
            int r_a = rw + lr;
            float bc0 = b1[col], bc1 = b1[col + 1];
            uint2 u0, u1;
            u0.x = f2tf32(fmaxf(acc[nt][0] + bc0, 0.f));
            u0.y = f2tf32(fmaxf(acc[nt][1] + bc1, 0.f));
            u1.x = f2tf32(fmaxf(acc[nt][2] + bc0, 0.f));
            u1.y = f2tf32(fmaxf(acc[nt][3] + bc1, 0.f));
            *(uint2*)(Abuf + r_a * SA + col)       = u0;
            *(uint2*)(Abuf + (r_a + 8) * SA + col) = u1;
            acc[nt][0] = acc[nt][1] = 0.f;
            acc[nt][2] = acc[nt][3] = 0.f;
        }
        __syncthreads();

        // ---- GEMM 2: acc = h1 @ W2^T ----
#pragma unroll 4
        for (int ks = 0; ks < 16; ++ks) {
            const int k0 = ks * 8;
            unsigned a[4];
            {
                const float* p = Abuf + (rw + lr) * SA + k0 + lc;
                a[0] = __float_as_uint(p[0]);
                a[1] = __float_as_uint(p[8 * SA]);
                a[2] = __float_as_uint(p[4]);
                a[3] = __float_as_uint(p[8 * SA + 4]);
            }
            unsigned b[8][2];
#pragma unroll
            for (int nt = 0; nt < 8; ++nt) {
                const float* p = W2t + (k0 + lc) * SB + cw + 8 * nt + lr;
                b[nt][0] = __float_as_uint(p[0]);
                b[nt][1] = __float_as_uint(p[4 * SB]);
            }
#pragma unroll
            for (int nt = 0; nt < 8; ++nt) mma_tf32(acc[nt], a, b[nt]);
        }

        // Epilogue 2: bias + relu -> global.
#pragma unroll
        for (int nt = 0; nt < 8; ++nt) {
            int col = cw + 8 * nt + 2 * lc;
            int r_a = rw + lr;
            float bc0 = b2[col], bc1 = b2[col + 1];
            int row = row0 + r_a;
            if (row < n) {
                float2 v;
                v.x = fmaxf(acc[nt][0] + bc0, 0.f);
                v.y = fmaxf(acc[nt][1] + bc1, 0.f);
                *(float2*)(out + (long)row * D + col) = v;
            }
            if (row + 8 < n) {
                float2 v;
                v.x = fmaxf(acc[nt][2] + bc0, 0.f);
                v.y = fmaxf(acc[nt][3] + bc1, 0.f);
                *(float2*)(out + (long)(row + 8) * D + col) = v;
            }
        }
    }
}

// ---------------------------------------------------------------------------
extern "C" void kernel_launch(void* const* d_in, const int* in_sizes, int n_in,
                              void* d_out, int out_size) {
    const float* x  = (const float*)d_in[0];
    const int*   ei = (const int*)d_in[1];
    const float* W1 = (const float*)d_in[2];
    const float* b1 = (const float*)d_in[3];
    const float* W2 = (const float*)d_in[4];
    const float* b2 = (const float*)d_in[5];
    float* out = (float*)d_out;

    const int n = in_sizes[0] / D;
    const int E = in_sizes[1] / 2;
    const int* src = ei;
    const int* dst = ei + E;

    // K1: agg = 0 (grid-stride x4)
    {
        int total4 = n * (D / 4);
        zero_agg_kernel<<<1184, 256>>>(total4);
    }

    // K2: bulk-reduce scatter (one-shot blocks)
    {
        int blocks = (E + EPB - 1) / EPB;
        scatter_bulk_kernel<<<blocks, 128>>>(x, src, dst, E);
    }

    // K3: persistent fused tf32 MLP, 64-row tiles
    {
        int smem = (TROWS * SA + 2 * 128 * SB) * (int)sizeof(float);  // 173056 B
        cudaFuncSetAttribute(mlp_kernel,
                             cudaFuncAttributeMaxDynamicSharedMemorySize, smem);
        int numTiles = (n + TROWS - 1) / TROWS;
        mlp_kernel<<<148, 256, smem>>>(x, W1, b1, W2, b2, out, n, numTiles);
    }
}

// round 14
// speedup vs baseline: 1.5072x; 1.5072x over previous
#include <cuda_runtime.h>
#include <cuda_bf16.h>

// ---------------------------------------------------------------------------
// GIN layer: out = relu( relu( (x + scatter_sum(x[src] -> dst)) @ W1^T + b1 ) @ W2^T + b2 )
// N = 100000, D = 128, E = 625000.
//
// R14: revert R12 regressions (zero kernel + 64-row tiles); R11 config
//      restored; scatter batches 64 edges per block (EPB 32->64).
//   K1: agg = 0                   (1 float4/thread, R11 proven)
//   K2: bulk-reduce scatter       (one-shot, 64 edges/block, 256 thr)
//   K3: persistent fused tf32 MLP (R11 proven: 128-row tiles, reg prefetch)
// ---------------------------------------------------------------------------

#define D 128
#define MAX_N 100000
#define SA 132
#define SB 136
#define EPB 64           // edges per block in the scatter

__device__ float g_agg[(size_t)MAX_N * D];

// ---------------------------------------------------------------------------
__global__ void zero_agg_kernel(int total4) {
    int i = blockIdx.x * blockDim.x + threadIdx.x;
    if (i < total4) ((float4*)g_agg)[i] = make_float4(0.f, 0.f, 0.f, 0.f);
}

// ---------------------------------------------------------------------------
__device__ __forceinline__ unsigned smem_u32(const void* p) {
    unsigned a;
    asm("{ .reg .u64 t; cvta.to.shared.u64 t, %1; cvt.u32.u64 %0, t; }"
        : "=r"(a) : "l"(p));
    return a;
}

// One-shot bulk-reduce scatter. Block = 256 threads, EPB=64 edges (32 KB smem).
__global__ __launch_bounds__(256, 4)
void scatter_bulk_kernel(const float* __restrict__ x,
                         const int* __restrict__ src,
                         const int* __restrict__ dst,
                         int E) {
    __shared__ __align__(16) float buf[EPB][D];   // 32 KB

    const int tid = threadIdx.x;
    const int e0  = blockIdx.x * EPB;

    // Stage: r = tid>>2 covers 64 rows, c0 = tid&3; each thread loads
    // 8 float4 spread across its row (32 float4 per row).
    {
        const int r  = tid >> 2;          // 0..63: row
        const int c0 = tid & 3;           // 0..3
        int e = e0 + r;
        if (e < E) {
            const float4* xs = (const float4*)(x + (long)src[e] * D);
            float4* bb = (float4*)&buf[r][0];
#pragma unroll
            for (int q = 0; q < 8; ++q) {
                bb[c0 + q * 4] = xs[c0 + q * 4];
            }
        }
    }
    __syncthreads();
    asm volatile("fence.proxy.async.shared::cta;" ::: "memory");

    // Threads 0..63 each issue one 512 B bulk reduce.
    if (tid < EPB) {
        int e = e0 + tid;
        if (e < E) {
            unsigned saddr = smem_u32(&buf[tid][0]);
            float* g = g_agg + (long)dst[e] * D;
            asm volatile(
                "cp.reduce.async.bulk.global.shared::cta.bulk_group.add.f32 "
                "[%0], [%1], 512;"
                :: "l"(g), "r"(saddr) : "memory");
        }
        asm volatile("cp.async.bulk.commit_group;" ::: "memory");
        asm volatile("cp.async.bulk.wait_group 0;" ::: "memory");
    }
}

// ---------------------------------------------------------------------------
__device__ __forceinline__ unsigned f2tf32(float f) {
    unsigned r;
    asm("cvt.rna.tf32.f32 %0, %1;" : "=r"(r) : "f"(f));
    return r;
}

__device__ __forceinline__ void mma_tf32(float c[4], const unsigned a[4],
                                         const unsigned b[2]) {
    asm volatile(
        "mma.sync.aligned.m16n8k8.row.col.f32.tf32.tf32.f32 "
        "{%0,%1,%2,%3}, {%4,%5,%6,%7}, {%8,%9}, {%0,%1,%2,%3};"
        : "+f"(c[0]), "+f"(c[1]), "+f"(c[2]), "+f"(c[3])
        : "r"(a[0]), "r"(a[1]), "r"(a[2]), "r"(a[3]), "r"(b[0]), "r"(b[1]));
}

// ---------------------------------------------------------------------------
// Persistent fused MLP (R11 proven). Grid = 148 CTAs x 256 threads.
// 128-row tiles; warp tile 32 rows x 64 cols (2 m-tiles x 8 n-tiles).
__global__ __launch_bounds__(256, 1)
void mlp_kernel(const float* __restrict__ x,
                const float* __restrict__ W1, const float* __restrict__ b1,
                const float* __restrict__ W2, const float* __restrict__ b2,
                float* __restrict__ out, int n, int numTiles) {
    extern __shared__ float sm[];
    float* Abuf = sm;                     // 128*SA
    float* W1t  = sm + 128 * SA;          // 128*SB
    float* W2t  = W1t + 128 * SB;         // 128*SB

    const int tid  = threadIdx.x;
    const int w    = tid >> 5;
    const int lane = tid & 31;
    const int lr   = lane >> 2;
    const int lc   = lane & 3;
    const int rw   = (w & 3) * 32;
    const int cw   = (w >> 2) * 64;
    const int i0   = tid >> 5;
    const int k4   = tid & 31;

    for (int idx = tid; idx < D * D; idx += 256) {
        int nn = idx >> 7;
        int m  = idx & 127;
        W1t[m * SB + nn] = __uint_as_float(f2tf32(W1[idx]));
        W2t[m * SB + nn] = __uint_as_float(f2tf32(W2[idx]));
    }

    float4 r[16];
    int t = blockIdx.x;
    {
        int base = t * 128;
#pragma unroll
        for (int q = 0; q < 16; ++q) {
            int row = base + i0 + 8 * q;
            float4 v = make_float4(0.f, 0.f, 0.f, 0.f);
            if (row < n) {
                float4 vx = *(const float4*)(x + (long)row * D + k4 * 4);
                float4 vg = *(const float4*)(g_agg + (long)row * D + k4 * 4);
                v.x = vx.x + vg.x; v.y = vx.y + vg.y;
                v.z = vx.z + vg.z; v.w = vx.w + vg.w;
            }
            r[q] = v;
        }
    }

    for (; t < numTiles; t += gridDim.x) {
        const int row0 = t * 128;

        __syncthreads();

#pragma unroll
        for (int q = 0; q < 16; ++q) {
            uint4 u;
            u.x = f2tf32(r[q].x); u.y = f2tf32(r[q].y);
            u.z = f2tf32(r[q].z); u.w = f2tf32(r[q].w);
            *(uint4*)(Abuf + (i0 + 8 * q) * SA + k4 * 4) = u;
        }
        __syncthreads();

        int tn = t + gridDim.x;
        if (tn < numTiles) {
            int base = tn * 128;
#pragma unroll
            for (int q = 0; q < 16; ++q) {
                int row = base + i0 + 8 * q;
                float4 v = make_float4(0.f, 0.f, 0.f, 0.f);
                if (row < n) {
                    float4 vx = *(const float4*)(x + (long)row * D + k4 * 4);
                    float4 vg = *(const float4*)(g_agg + (long)row * D + k4 * 4);
                    v.x = vx.x + vg.x; v.y = vx.y + vg.y;
                    v.z = vx.z + vg.z; v.w = vx.w + vg.w;
                }
                r[q] = v;
            }
        }

        float acc[2][8][4];
#pragma unroll
        for (int mt = 0; mt < 2; ++mt)
#pragma unroll
            for (int nt = 0; nt < 8; ++nt)
#pragma unroll
                for (int q = 0; q < 4; ++q) acc[mt][nt][q] = 0.f;

        // ---- GEMM 1 ----
#pragma unroll 4
        for (int ks = 0; ks < 16; ++ks) {
            const int k0 = ks * 8;
            unsigned a[2][4];
#pragma unroll
            for (int mt = 0; mt < 2; ++mt) {
                const float* p = Abuf + (rw + 16 * mt + lr) * SA + k0 + lc;
                a[mt][0] = __float_as_uint(p[0]);
                a[mt][1] = __float_as_uint(p[8 * SA]);
                a[mt][2] = __float_as_uint(p[4]);
                a[mt][3] = __float_as_uint(p[8 * SA + 4]);
            }
            unsigned b[8][2];
#pragma unroll
            for (int nt = 0; nt < 8; ++nt) {
                const float* p = W1t + (k0 + lc) * SB + cw + 8 * nt + lr;
                b[nt][0] = __float_as_uint(p[0]);
                b[nt][1] = __float_as_uint(p[4 * SB]);
            }
#pragma unroll
            for (int mt = 0; mt < 2; ++mt)
#pragma unroll
                for (int nt = 0; nt < 8; ++nt) mma_tf32(acc[mt][nt], a[mt], b[nt]);
        }
        __syncthreads();

        // Epilogue 1: bias + relu -> h1 (tf32) in Abuf.
#pragma unroll
        for (int mt = 0; mt < 2; ++mt) {
#pragma unroll
            for (int nt = 0; nt < 8; ++nt) {
                int col = cw + 8 * nt + 2 * lc;
                int r_a = rw + 16 * mt + lr;
                float bc0 = b1[col], bc1 = b1[col + 1];
                uint2 u0, u1;
                u0.x = f2tf32(fmaxf(acc[mt][nt][0] + bc0, 0.f));
                u0.y = f2tf32(fmaxf(acc[mt][nt][1] + bc1, 0.f));
                u1.x = f2tf32(fmaxf(acc[mt][nt][2] + bc0, 0.f));
                u1.y = f2tf32(fmaxf(acc[mt][nt][3] + bc1, 0.f));
                *(uint2*)(Abuf + r_a * SA + col)       = u0;
                *(uint2*)(Abuf + (r_a + 8) * SA + col) = u1;
                acc[mt][nt][0] = acc[mt][nt][1] = 0.f;
                acc[mt][nt][2] = acc[mt][nt][3] = 0.f;
            }
        }
        __syncthreads();

        // ---- GEMM 2 ----
#pragma unroll 4
        for (int ks = 0; ks < 16; ++ks) {
            const int k0 = ks * 8;
            unsigned a[2][4];
#pragma unroll
            for (int mt = 0; mt < 2; ++mt) {
                const float* p = Abuf + (rw + 16 * mt + lr) * SA + k0 + lc;
                a[mt][0] = __float_as_uint(p[0]);
                a[mt][1] = __float_as_uint(p[8 * SA]);
                a[mt][2] = __float_as_uint(p[4]);
                a[mt][3] = __float_as_uint(p[8 * SA + 4]);
            }
            unsigned b[8][2];
#pragma unroll
            for (int nt = 0; nt < 8; ++nt) {
                const float* p = W2t + (k0 + lc) * SB + cw + 8 * nt + lr;
                b[nt][0] = __float_as_uint(p[0]);
                b[nt][1] = __float_as_uint(p[4 * SB]);
            }
#pragma unroll
            for (int mt = 0; mt < 2; ++mt)
#pragma unroll
                for (int nt = 0; nt < 8; ++nt) mma_tf32(acc[mt][nt], a[mt], b[nt]);
        }

        // Epilogue 2: bias + relu -> global.
#pragma unroll
        for (int mt = 0; mt < 2; ++mt) {
#pragma unroll
            for (int nt = 0; nt < 8; ++nt) {
                int col = cw + 8 * nt + 2 * lc;
                int r_a = rw + 16 * mt + lr;
                float bc0 = b2[col], bc1 = b2[col + 1];
                int row = row0 + r_a;
                if (row < n) {
                    float2 v;
                    v.x = fmaxf(acc[mt][nt][0] + bc0, 0.f);
                    v.y = fmaxf(acc[mt][nt][1] + bc1, 0.f);
                    *(float2*)(out + (long)row * D + col) = v;
                }
                if (row + 8 < n) {
                    float2 v;
                    v.x = fmaxf(acc[mt][nt][2] + bc0, 0.f);
                    v.y = fmaxf(acc[mt][nt][3] + bc1, 0.f);
                    *(float2*)(out + (long)(row + 8) * D + col) = v;
                }
            }
        }
    }
}

// ---------------------------------------------------------------------------
extern "C" void kernel_launch(void* const* d_in, const int* in_sizes, int n_in,
                              void* d_out, int out_size) {
    const float* x  = (const float*)d_in[0];
    const int*   ei = (const int*)d_in[1];
    const float* W1 = (const float*)d_in[2];
    const float* b1 = (const float*)d_in[3];
    const float* W2 = (const float*)d_in[4];
    const float* b2 = (const float*)d_in[5];
    float* out = (float*)d_out;

    const int n = in_sizes[0] / D;
    const int E = in_sizes[1] / 2;
    const int* src = ei;
    const int* dst = ei + E;

    // K1: agg = 0
    {
        int total4 = n * (D / 4);
        int blocks = (total4 + 255) / 256;
        zero_agg_kernel<<<blocks, 256>>>(total4);
    }

    // K2: bulk-reduce scatter (one-shot, 64 edges/block)
    {
        int blocks = (E + EPB - 1) / EPB;
        scatter_bulk_kernel<<<blocks, 256>>>(x, src, dst, E);
    }

    // K3: persistent fused tf32 MLP (128-row tiles)
    {
        int smem = (128 * SA + 2 * 128 * SB) * (int)sizeof(float);  // 206848 B
        cudaFuncSetAttribute(mlp_kernel,
                             cudaFuncAttributeMaxDynamicSharedMemorySize, smem);
        int numTiles = (n + 127) / 128;
        mlp_kernel<<<148, 256, smem>>>(x, W1, b1, W2, b2, out, n, numTiles);
    }
}

// round 15
// speedup vs baseline: 1.6676x; 1.1064x over previous
#include <cuda_runtime.h>
#include <cuda_bf16.h>

// ---------------------------------------------------------------------------
// GIN layer: out = relu( relu( (x + scatter_sum(x[src] -> dst)) @ W1^T + b1 ) @ W2^T + b2 )
// N = 100000, D = 128, E = 625000.
//
// R15: EPB back to 32 (64 regressed); scatter made warp-autonomous:
//      each warp stages 8 rows (1 float4/lane, fully coalesced), fences,
//      issues 8 bulk reduces, waits -- no __syncthreads coupling.
//   K1: agg = 0                   (1 float4/thread, proven)
//   K2: warp-autonomous bulk-reduce scatter (32 edges/block)
//   K3: persistent fused tf32 MLP (R11 proven: 128-row tiles, reg prefetch)
// ---------------------------------------------------------------------------

#define D 128
#define MAX_N 100000
#define SA 132
#define SB 136
#define EPB 32           // edges per block in the scatter

__device__ float g_agg[(size_t)MAX_N * D];

// ---------------------------------------------------------------------------
__global__ void zero_agg_kernel(int total4) {
    int i = blockIdx.x * blockDim.x + threadIdx.x;
    if (i < total4) ((float4*)g_agg)[i] = make_float4(0.f, 0.f, 0.f, 0.f);
}

// ---------------------------------------------------------------------------
__device__ __forceinline__ unsigned smem_u32(const void* p) {
    unsigned a;
    asm("{ .reg .u64 t; cvta.to.shared.u64 t, %1; cvt.u32.u64 %0, t; }"
        : "=r"(a) : "l"(p));
    return a;
}

// Warp-autonomous bulk-reduce scatter. Block = 128 threads (4 warps),
// EPB = 32 edges; each warp owns 8 edges, no block-wide sync.
__global__ __launch_bounds__(128, 8)
void scatter_bulk_kernel(const float* __restrict__ x,
                         const int* __restrict__ src,
                         const int* __restrict__ dst,
                         int E) {
    __shared__ __align__(16) float buf[EPB][D];   // 16 KB

    const int tid  = threadIdx.x;
    const int w    = tid >> 5;     // warp 0..3
    const int lane = tid & 31;
    const int e0   = blockIdx.x * EPB + w * 8;    // this warp's first edge

    // Stage 8 rows: whole warp loads each row as one coalesced 512 B load.
#pragma unroll
    for (int q = 0; q < 8; ++q) {
        int e = e0 + q;
        if (e < E) {
            const float4* xs = (const float4*)(x + (long)src[e] * D);
            ((float4*)&buf[w * 8 + q][0])[lane] = xs[lane];
        }
    }
    __syncwarp();
    asm volatile("fence.proxy.async.shared::cta;" ::: "memory");

    // Lanes 0..7 each issue one 512 B bulk reduce for this warp's rows.
    if (lane < 8) {
        int e = e0 + lane;
        if (e < E) {
            unsigned saddr = smem_u32(&buf[w * 8 + lane][0]);
            float* g = g_agg + (long)dst[e] * D;
            asm volatile(
                "cp.reduce.async.bulk.global.shared::cta.bulk_group.add.f32 "
                "[%0], [%1], 512;"
                :: "l"(g), "r"(saddr) : "memory");
        }
        asm volatile("cp.async.bulk.commit_group;" ::: "memory");
        asm volatile("cp.async.bulk.wait_group 0;" ::: "memory");
    }
}

// ---------------------------------------------------------------------------
__device__ __forceinline__ unsigned f2tf32(float f) {
    unsigned r;
    asm("cvt.rna.tf32.f32 %0, %1;" : "=r"(r) : "f"(f));
    return r;
}

__device__ __forceinline__ void mma_tf32(float c[4], const unsigned a[4],
                                         const unsigned b[2]) {
    asm volatile(
        "mma.sync.aligned.m16n8k8.row.col.f32.tf32.tf32.f32 "
        "{%0,%1,%2,%3}, {%4,%5,%6,%7}, {%8,%9}, {%0,%1,%2,%3};"
        : "+f"(c[0]), "+f"(c[1]), "+f"(c[2]), "+f"(c[3])
        : "r"(a[0]), "r"(a[1]), "r"(a[2]), "r"(a[3]), "r"(b[0]), "r"(b[1]));
}

// ---------------------------------------------------------------------------
// Persistent fused MLP (R11 proven). Grid = 148 CTAs x 256 threads.
// 128-row tiles; warp tile 32 rows x 64 cols (2 m-tiles x 8 n-tiles).
__global__ __launch_bounds__(256, 1)
void mlp_kernel(const float* __restrict__ x,
                const float* __restrict__ W1, const float* __restrict__ b1,
                const float* __restrict__ W2, const float* __restrict__ b2,
                float* __restrict__ out, int n, int numTiles) {
    extern __shared__ float sm[];
    float* Abuf = sm;                     // 128*SA
    float* W1t  = sm + 128 * SA;          // 128*SB
    float* W2t  = W1t + 128 * SB;         // 128*SB

    const int tid  = threadIdx.x;
    const int w    = tid >> 5;
    const int lane = tid & 31;
    const int lr   = lane >> 2;
    const int lc   = lane & 3;
    const int rw   = (w & 3) * 32;
    const int cw   = (w >> 2) * 64;
    const int i0   = tid >> 5;
    const int k4   = tid & 31;

    for (int idx = tid; idx < D * D; idx += 256) {
        int nn = idx >> 7;
        int m  = idx & 127;
        W1t[m * SB + nn] = __uint_as_float(f2tf32(W1[idx]));
        W2t[m * SB + nn] = __uint_as_float(f2tf32(W2[idx]));
    }

    float4 r[16];
    int t = blockIdx.x;
    {
        int base = t * 128;
#pragma unroll
        for (int q = 0; q < 16; ++q) {
            int row = base + i0 + 8 * q;
            float4 v = make_float4(0.f, 0.f, 0.f, 0.f);
            if (row < n) {
                float4 vx = *(const float4*)(x + (long)row * D + k4 * 4);
                float4 vg = *(const float4*)(g_agg + (long)row * D + k4 * 4);
                v.x = vx.x + vg.x; v.y = vx.y + vg.y;
                v.z = vx.z + vg.z; v.w = vx.w + vg.w;
            }
            r[q] = v;
        }
    }

    for (; t < numTiles; t += gridDim.x) {
        const int row0 = t * 128;

        __syncthreads();

#pragma unroll
        for (int q = 0; q < 16; ++q) {
            uint4 u;
            u.x = f2tf32(r[q].x); u.y = f2tf32(r[q].y);
            u.z = f2tf32(r[q].z); u.w = f2tf32(r[q].w);
            *(uint4*)(Abuf + (i0 + 8 * q) * SA + k4 * 4) = u;
        }
        __syncthreads();

        int tn = t + gridDim.x;
        if (tn < numTiles) {
            int base = tn * 128;
#pragma unroll
            for (int q = 0; q < 16; ++q) {
                int row = base + i0 + 8 * q;
                float4 v = make_float4(0.f, 0.f, 0.f, 0.f);
                if (row < n) {
                    float4 vx = *(const float4*)(x + (long)row * D + k4 * 4);
                    float4 vg = *(const float4*)(g_agg + (long)row * D + k4 * 4);
                    v.x = vx.x + vg.x; v.y = vx.y + vg.y;
                    v.z = vx.z + vg.z; v.w = vx.w + vg.w;
                }
                r[q] = v;
            }
        }

        float acc[2][8][4];
#pragma unroll
        for (int mt = 0; mt < 2; ++mt)
#pragma unroll
            for (int nt = 0; nt < 8; ++nt)
#pragma unroll
                for (int q = 0; q < 4; ++q) acc[mt][nt][q] = 0.f;

        // ---- GEMM 1 ----
#pragma unroll 4
        for (int ks = 0; ks < 16; ++ks) {
            const int k0 = ks * 8;
            unsigned a[2][4];
#pragma unroll
            for (int mt = 0; mt < 2; ++mt) {
                const float* p = Abuf + (rw + 16 * mt + lr) * SA + k0 + lc;
                a[mt][0] = __float_as_uint(p[0]);
                a[mt][1] = __float_as_uint(p[8 * SA]);
                a[mt][2] = __float_as_uint(p[4]);
                a[mt][3] = __float_as_uint(p[8 * SA + 4]);
            }
            unsigned b[8][2];
#pragma unroll
            for (int nt = 0; nt < 8; ++nt) {
                const float* p = W1t + (k0 + lc) * SB + cw + 8 * nt + lr;
                b[nt][0] = __float_as_uint(p[0]);
                b[nt][1] = __float_as_uint(p[4 * SB]);
            }
#pragma unroll
            for (int mt = 0; mt < 2; ++mt)
#pragma unroll
                for (int nt = 0; nt < 8; ++nt) mma_tf32(acc[mt][nt], a[mt], b[nt]);
        }
        __syncthreads();

        // Epilogue 1: bias + relu -> h1 (tf32) in Abuf.
#pragma unroll
        for (int mt = 0; mt < 2; ++mt) {
#pragma unroll
            for (int nt = 0; nt < 8; ++nt) {
                int col = cw + 8 * nt + 2 * lc;
                int r_a = rw + 16 * mt + lr;
                float bc0 = b1[col], bc1 = b1[col + 1];
                uint2 u0, u1;
                u0.x = f2tf32(fmaxf(acc[mt][nt][0] + bc0, 0.f));
                u0.y = f2tf32(fmaxf(acc[mt][nt][1] + bc1, 0.f));
                u1.x = f2tf32(fmaxf(acc[mt][nt][2] + bc0, 0.f));
                u1.y = f2tf32(fmaxf(acc[mt][nt][3] + bc1, 0.f));
                *(uint2*)(Abuf + r_a * SA + col)       = u0;
                *(uint2*)(Abuf + (r_a + 8) * SA + col) = u1;
                acc[mt][nt][0] = acc[mt][nt][1] = 0.f;
                acc[mt][nt][2] = acc[mt][nt][3] = 0.f;
            }
        }
        __syncthreads();

        // ---- GEMM 2 ----
#pragma unroll 4
        for (int ks = 0; ks < 16; ++ks) {
            const int k0 = ks * 8;
            unsigned a[2][4];
#pragma unroll
            for (int mt = 0; mt < 2; ++mt) {
                const float* p = Abuf + (rw + 16 * mt + lr) * SA + k0 + lc;
                a[mt][0] = __float_as_uint(p[0]);
                a[mt][1] = __float_as_uint(p[8 * SA]);
                a[mt][2] = __float_as_uint(p[4]);
                a[mt][3] = __float_as_uint(p[8 * SA + 4]);
            }
            unsigned b[8][2];
#pragma unroll
            for (int nt = 0; nt < 8; ++nt) {
                const float* p = W2t + (k0 + lc) * SB + cw + 8 * nt + lr;
                b[nt][0] = __float_as_uint(p[0]);
                b[nt][1] = __float_as_uint(p[4 * SB]);
            }
#pragma unroll
            for (int mt = 0; mt < 2; ++mt)
#pragma unroll
                for (int nt = 0; nt < 8; ++nt) mma_tf32(acc[mt][nt], a[mt], b[nt]);
        }

        // Epilogue 2: bias + relu -> global.
#pragma unroll
        for (int mt = 0; mt < 2; ++mt) {
#pragma unroll
            for (int nt = 0; nt < 8; ++nt) {
                int col = cw + 8 * nt + 2 * lc;
                int r_a = rw + 16 * mt + lr;
                float bc0 = b2[col], bc1 = b2[col + 1];
                int row = row0 + r_a;
                if (row < n) {
                    float2 v;
                    v.x = fmaxf(acc[mt][nt][0] + bc0, 0.f);
                    v.y = fmaxf(acc[mt][nt][1] + bc1, 0.f);
                    *(float2*)(out + (long)row * D + col) = v;
                }
                if (row + 8 < n) {
                    float2 v;
                    v.x = fmaxf(acc[mt][nt][2] + bc0, 0.f);
                    v.y = fmaxf(acc[mt][nt][3] + bc1, 0.f);
                    *(float2*)(out + (long)(row + 8) * D + col) = v;
                }
            }
        }
    }
}

// ---------------------------------------------------------------------------
extern "C" void kernel_launch(void* const* d_in, const int* in_sizes, int n_in,
                              void* d_out, int out_size) {
    const float* x  = (const float*)d_in[0];
    const int*   ei = (const int*)d_in[1];
    const float* W1 = (const float*)d_in[2];
    const float* b1 = (const float*)d_in[3];
    const float* W2 = (const float*)d_in[4];
    const float* b2 = (const float*)d_in[5];
    float* out = (float*)d_out;

    const int n = in_sizes[0] / D;
    const int E = in_sizes[1] / 2;
    const int* src = ei;
    const int* dst = ei + E;

    // K1: agg = 0
    {
        int total4 = n * (D / 4);
        int blocks = (total4 + 255) / 256;
        zero_agg_kernel<<<blocks, 256>>>(total4);
    }

    // K2: warp-autonomous bulk-reduce scatter
    {
        int blocks = (E + EPB - 1) / EPB;
        scatter_bulk_kernel<<<blocks, 128>>>(x, src, dst, E);
    }

    // K3: persistent fused tf32 MLP (128-row tiles)
    {
        int smem = (128 * SA + 2 * 128 * SB) * (int)sizeof(float);  // 206848 B
        cudaFuncSetAttribute(mlp_kernel,
                             cudaFuncAttributeMaxDynamicSharedMemorySize, smem);
        int numTiles = (n + 127) / 128;
        mlp_kernel<<<148, 256, smem>>>(x, W1, b1, W2, b2, out, n, numTiles);
    }
}